// round 16
// baseline (speedup 1.0000x reference)
#include <cuda_runtime.h>
#include <cuda_bf16.h>
#include <math.h>

#define BATCH 1024
#define SEQ   1024
#define TAGS  32
#define ITERS 511          // main-loop iterations per direction
#define PF    8            // emit prefetch ring depth

#define FB_BLOCKS   (BATCH / 2)          // 512: forward/backward blocks
#define GOLD_BLOCKS (BATCH)              // 1024: one gold block per batch
#define ALL_BLOCKS  (FB_BLOCKS + GOLD_BLOCKS)

__device__ float g_logz[BATCH];
__device__ float g_gold[BATCH];
__device__ unsigned int g_ticket;

// ---------- packed f32x2 helpers (sm_103a FFMA2 path, PTX-only) ----------
__device__ __forceinline__ unsigned long long pk2(float x, float y) {
    unsigned long long r;
    asm("mov.b64 %0, {%1, %2};" : "=l"(r) : "f"(x), "f"(y));
    return r;
}
__device__ __forceinline__ void upk2(unsigned long long a, float& x, float& y) {
    asm("mov.b64 {%0, %1}, %2;" : "=f"(x), "=f"(y) : "l"(a));
}
__device__ __forceinline__ unsigned long long mul2(unsigned long long a, unsigned long long b) {
    unsigned long long d;
    asm("mul.rn.f32x2 %0, %1, %2;" : "=l"(d) : "l"(a), "l"(b));
    return d;
}
__device__ __forceinline__ unsigned long long fma2(unsigned long long a, unsigned long long b, unsigned long long c) {
    unsigned long long d;
    asm("fma.rn.f32x2 %0, %1, %2, %3;" : "=l"(d) : "l"(a), "l"(b), "l"(c));
    return d;
}
__device__ __forceinline__ unsigned long long add2(unsigned long long a, unsigned long long b) {
    unsigned long long d;
    asm("add.rn.f32x2 %0, %1, %2;" : "=l"(d) : "l"(a), "l"(b));
    return d;
}
__device__ __forceinline__ float ex2f(float x) {
    float y; asm("ex2.approx.f32 %0, %1;" : "=f"(y) : "f"(x)); return y;
}
__device__ __forceinline__ float lg2f(float x) {
    float y; asm("lg2.approx.f32 %0, %1;" : "=f"(y) : "f"(x)); return y;
}
__device__ __forceinline__ float rcpf(float x) {
    float y; asm("rcp.approx.f32 %0, %1;" : "=f"(y) : "f"(x)); return y;
}

#define LOG2E 1.4426950408889634f
#define LN2   0.6931471805599453f

// Half-split matvec: lane loads only its 16-value half of w (4x LDS.128),
// computes partials for output j (ea) and partner output j^16 (eb), then one
// shfl.xor(16) completes both dot products.
__device__ __forceinline__ float matvec_half(const float* wb_half,
                                             const unsigned long long* ea,
                                             const unsigned long long* eb) {
    const ulonglong2* w4 = (const ulonglong2*)wb_half;
    ulonglong2 q0 = w4[0], q1 = w4[1];
    unsigned long long pa0 = mul2(q0.x, ea[0]);
    unsigned long long pa1 = mul2(q0.y, ea[1]);
    unsigned long long pb0 = mul2(q0.x, eb[0]);
    unsigned long long pb1 = mul2(q0.y, eb[1]);
    pa0 = fma2(q1.x, ea[2], pa0);
    pa1 = fma2(q1.y, ea[3], pa1);
    pb0 = fma2(q1.x, eb[2], pb0);
    pb1 = fma2(q1.y, eb[3], pb1);
    ulonglong2 q2 = w4[2], q3 = w4[3];
    pa0 = fma2(q2.x, ea[4], pa0);
    pa1 = fma2(q2.y, ea[5], pa1);
    pb0 = fma2(q2.x, eb[4], pb0);
    pb1 = fma2(q2.y, eb[5], pb1);
    pa0 = fma2(q3.x, ea[6], pa0);
    pa1 = fma2(q3.y, ea[7], pa1);
    pb0 = fma2(q3.x, eb[6], pb0);
    pb1 = fma2(q3.y, eb[7], pb1);
    pa0 = add2(pa0, pa1);
    pb0 = add2(pb0, pb1);
    float al, ah, bl, bh;
    upk2(pa0, al, ah);
    upk2(pb0, bl, bh);
    float fa = al + ah;                 // my-half partial for output j
    float fb = bl + bh;                 // my-half partial for output j^16
    return fa + __shfl_xor_sync(0xffffffffu, fb, 16);
}

// ---------------------------------------------------------------------------
// fb path: 2 batches per block (128 threads):
//   warp 0: fwd b0   warp 1: bwd b0   warp 2: fwd b1   warp 3: bwd b1
// Prob-space recursion, renorm every 4 steps via off-path shfl(u,0).
// Meet: Z = sum_k (E^T alpha_511)_k gamma_512(k)
// ---------------------------------------------------------------------------
__device__ void fb_path(const float* __restrict__ logits,
                        const float* __restrict__ trans,
                        int blk) {
    const int w   = threadIdx.x >> 5;     // warp in block (0..3)
    const int j   = threadIdx.x & 31;     // lane = tag
    const int bi  = w >> 1;               // batch within block (0/1)
    const int dir = w & 1;                // 0 = fwd, 1 = bwd
    const int b   = blk * 2 + bi;

    __shared__ __align__(16) float sbuf[4][2][32];  // [warp][parity][vec]
    __shared__ float xg[2][32];                     // gamma_512 exchange
    __shared__ float xacc[2];                       // bwd log-scale exchange

    const int h  = (j >> 4) << 4;         // my half's base index (0 or 16)
    const int jp = j ^ 16;                // partner output tag

    unsigned long long ea[8], eb[8];
    if (dir == 0) {
#pragma unroll
        for (int k = 0; k < 8; k++) {
            ea[k] = pk2(expf(trans[(h + 2 * k) * TAGS + j]),
                        expf(trans[(h + 2 * k + 1) * TAGS + j]));
            eb[k] = pk2(expf(trans[(h + 2 * k) * TAGS + jp]),
                        expf(trans[(h + 2 * k + 1) * TAGS + jp]));
        }
    } else {
#pragma unroll
        for (int k = 0; k < 8; k++) {
            ea[k] = pk2(expf(trans[j * TAGS + h + 2 * k]),
                        expf(trans[j * TAGS + h + 2 * k + 1]));
            eb[k] = pk2(expf(trans[jp * TAGS + h + 2 * k]),
                        expf(trans[jp * TAGS + h + 2 * k + 1]));
        }
    }

    const float* lg = logits + (size_t)b * (SEQ * TAGS);

    float e0 = (dir == 0) ? lg[j] : lg[(SEQ - 1) * TAGS + j];
    float m0 = __shfl_sync(0xffffffffu, e0, 0);
    float u      = ex2f((e0 - m0) * LOG2E);
    float logacc = m0;

    const int estep = (dir == 0) ? TAGS : -TAGS;
    const float* ep = (dir == 0) ? (lg + TAGS + j)
                                 : (lg + (SEQ - 2) * TAGS + j);
    float r[PF];
#pragma unroll
    for (int k = 0; k < PF; k++)
        r[k] = ep[k * estep];
    const float* pl = ep + PF * estep;

    float* wb0 = &sbuf[w][0][0];
    float* wb1 = &sbuf[w][1][0];

#pragma unroll 8
    for (int it = 0; it < ITERS; ++it) {
        float u0 = 0.0f;
        if ((it & 3) == 0)
            u0 = __shfl_sync(0xffffffffu, u, 0);   // off-path renorm scale

        float emit = r[it & (PF - 1)];
        r[it & (PF - 1)] = *pl;             // refill same slot (needed it+8)
        pl += estep;

        float p = ex2f(emit * LOG2E);       // off the carried chain

        float* wb = (it & 1) ? wb1 : wb0;
        wb[j] = u;
        __syncwarp(0xffffffffu);

        float s = matvec_half(wb + h, ea, eb);
        float un = s * p;

        if ((it & 3) == 0) {
            un *= rcpf(u0);
            logacc += lg2f(u0) * LN2;       // off-path bookkeeping
        }
        u = un;
    }

    {
        float u0 = __shfl_sync(0xffffffffu, u, 0);
        u *= rcpf(u0);
        logacc += lg2f(u0) * LN2;
    }

    if (dir == 1) {
        xg[bi][j] = u;                      // gamma_512 (scaled)
        if (j == 0) xacc[bi] = logacc;
    }
    __syncthreads();

    if (dir == 0) {
        wb1[j] = u;
        __syncwarp(0xffffffffu);
        float s = matvec_half(wb1 + h, ea, eb);

        float prod = s * xg[bi][j];
#pragma unroll
        for (int k = 16; k; k >>= 1)
            prod += __shfl_xor_sync(0xffffffffu, prod, k);

        if (j == 0)
            g_logz[b] = lg2f(prod) * LN2 + logacc + xacc[bi];
    }
}

// ---------------------------------------------------------------------------
// gold path: one 128-thread block per batch, lanes stride the sequence.
// ---------------------------------------------------------------------------
__device__ void gold_path(const float* __restrict__ logits,
                          const float* __restrict__ trans,
                          const int* __restrict__ tags,
                          const int* __restrict__ lengths,
                          int b) {
    __shared__ float tr[TAGS * TAGS];
    __shared__ float sm[4];

    for (int i = threadIdx.x; i < TAGS * TAGS; i += 128)
        tr[i] = trans[i];
    __syncthreads();

    const int tid  = threadIdx.x;
    const int warp = tid >> 5;
    const int l    = tid & 31;

    const int*   tg = tags + (size_t)b * SEQ;
    const float* lg = logits + (size_t)b * (SEQ * TAGS);
    const int len = lengths[b];

    float acc = 0.0f;
    for (int s = tid; s < len; s += 128) {
        int t1 = __ldg(&tg[s]);
        acc += __ldg(&lg[s * TAGS + t1]);
        if (s > 0) {
            int t0 = __ldg(&tg[s - 1]);
            acc += tr[t0 * TAGS + t1];
        }
    }
#pragma unroll
    for (int k = 16; k; k >>= 1)
        acc += __shfl_xor_sync(0xffffffffu, acc, k);
    if (l == 0) sm[warp] = acc;
    __syncthreads();

    if (tid == 0)
        g_gold[b] = sm[0] + sm[1] + sm[2] + sm[3];
}

// ---------------------------------------------------------------------------
// Single heterogeneous-grid kernel:
//   blocks [0, FB_BLOCKS)              -> fb path (2 batches each)
//   blocks [FB_BLOCKS, ALL_BLOCKS)     -> gold path (1 batch each)
// Gold has no dependence on fb, so its 38MB of gathers overlap fb's
// latency-bound scan instead of serializing after it (block-level mixing;
// R9 showed warp-level mixing inside fb blocks is toxic, this is not that).
// Last block (ticket) does the deterministic tree reduction -> mean.
// ---------------------------------------------------------------------------
__global__ __launch_bounds__(128, 4)
void crf_all_kernel(const float* __restrict__ logits,
                    const float* __restrict__ trans,
                    const int* __restrict__ tags,
                    const int* __restrict__ lengths,
                    float* __restrict__ out) {
    __shared__ bool amLast;

    if (blockIdx.x < FB_BLOCKS) {
        fb_path(logits, trans, blockIdx.x);
    } else {
        gold_path(logits, trans, tags, lengths, blockIdx.x - FB_BLOCKS);
    }
    __syncthreads();

    if (threadIdx.x == 0) {
        __threadfence();
        unsigned int t = atomicAdd(&g_ticket, 1u);
        amLast = (t == (unsigned)(ALL_BLOCKS - 1));
    }
    __syncthreads();

    if (amLast) {
        __shared__ float red[128];
        const int tid = threadIdx.x;
        float a = 0.0f;
#pragma unroll
        for (int o = 0; o < 8; o++) {
            int i = tid + o * 128;
            a += __ldcg(&g_logz[i]) - __ldcg(&g_gold[i]);
        }
        red[tid] = a;
        __syncthreads();
#pragma unroll
        for (int k = 64; k; k >>= 1) {
            if (tid < k) red[tid] += red[tid + k];
            __syncthreads();
        }
        if (tid == 0) {
            out[0] = red[0] * (1.0f / 1024.0f);
            g_ticket = 0;                  // reset for next graph replay
        }
    }
}

extern "C" void kernel_launch(void* const* d_in, const int* in_sizes, int n_in,
                              void* d_out, int out_size) {
    const float* logits  = (const float*)d_in[0];
    const float* trans   = (const float*)d_in[1];
    const int*   tags    = (const int*)d_in[2];
    const int*   lengths = (const int*)d_in[3];
    float* out = (float*)d_out;

    crf_all_kernel<<<ALL_BLOCKS, 128>>>(logits, trans, tags, lengths, out);
}

// round 17
// speedup vs baseline: 1.0808x; 1.0808x over previous
#include <cuda_runtime.h>
#include <cuda_bf16.h>
#include <math.h>

#define BATCH 1024
#define SEQ   1024
#define TAGS  32
#define ITERS 511          // main-loop iterations per direction

__device__ float g_logz[BATCH];
__device__ float g_partial[BATCH];
__device__ unsigned int g_ticket;

// ---------- packed f32x2 helpers (sm_103a FFMA2 path, PTX-only) ----------
__device__ __forceinline__ unsigned long long pk2(float x, float y) {
    unsigned long long r;
    asm("mov.b64 %0, {%1, %2};" : "=l"(r) : "f"(x), "f"(y));
    return r;
}
__device__ __forceinline__ void upk2(unsigned long long a, float& x, float& y) {
    asm("mov.b64 {%0, %1}, %2;" : "=f"(x), "=f"(y) : "l"(a));
}
__device__ __forceinline__ unsigned long long mul2(unsigned long long a, unsigned long long b) {
    unsigned long long d;
    asm("mul.rn.f32x2 %0, %1, %2;" : "=l"(d) : "l"(a), "l"(b));
    return d;
}
__device__ __forceinline__ unsigned long long fma2(unsigned long long a, unsigned long long b, unsigned long long c) {
    unsigned long long d;
    asm("fma.rn.f32x2 %0, %1, %2, %3;" : "=l"(d) : "l"(a), "l"(b), "l"(c));
    return d;
}
__device__ __forceinline__ unsigned long long add2(unsigned long long a, unsigned long long b) {
    unsigned long long d;
    asm("add.rn.f32x2 %0, %1, %2;" : "=l"(d) : "l"(a), "l"(b));
    return d;
}
__device__ __forceinline__ float ex2f(float x) {
    float y; asm("ex2.approx.f32 %0, %1;" : "=f"(y) : "f"(x)); return y;
}
__device__ __forceinline__ float lg2f(float x) {
    float y; asm("lg2.approx.f32 %0, %1;" : "=f"(y) : "f"(x)); return y;
}
__device__ __forceinline__ float rcpf(float x) {
    float y; asm("rcp.approx.f32 %0, %1;" : "=f"(y) : "f"(x)); return y;
}

#define LOG2E 1.4426950408889634f
#define LN2   0.6931471805599453f

// Half-split matvec: lane loads only its 16-value half of w (4x LDS.128),
// computes partials for output j (ea) and partner output j^16 (eb), then one
// shfl.xor(16) completes both dot products.
__device__ __forceinline__ float matvec_half(const float* wb_half,
                                             const unsigned long long* ea,
                                             const unsigned long long* eb) {
    const ulonglong2* w4 = (const ulonglong2*)wb_half;
    ulonglong2 q0 = w4[0], q1 = w4[1];
    unsigned long long pa0 = mul2(q0.x, ea[0]);
    unsigned long long pa1 = mul2(q0.y, ea[1]);
    unsigned long long pb0 = mul2(q0.x, eb[0]);
    unsigned long long pb1 = mul2(q0.y, eb[1]);
    pa0 = fma2(q1.x, ea[2], pa0);
    pa1 = fma2(q1.y, ea[3], pa1);
    pb0 = fma2(q1.x, eb[2], pb0);
    pb1 = fma2(q1.y, eb[3], pb1);
    ulonglong2 q2 = w4[2], q3 = w4[3];
    pa0 = fma2(q2.x, ea[4], pa0);
    pa1 = fma2(q2.y, ea[5], pa1);
    pb0 = fma2(q2.x, eb[4], pb0);
    pb1 = fma2(q2.y, eb[5], pb1);
    pa0 = fma2(q3.x, ea[6], pa0);
    pa1 = fma2(q3.y, ea[7], pa1);
    pb0 = fma2(q3.x, eb[6], pb0);
    pb1 = fma2(q3.y, eb[7], pb1);
    pa0 = add2(pa0, pa1);
    pb0 = add2(pb0, pb1);
    float al, ah, bl, bh;
    upk2(pa0, al, ah);
    upk2(pb0, bl, bh);
    float fa = al + ah;                 // my-half partial for output j
    float fb = bl + bh;                 // my-half partial for output j^16
    return fa + __shfl_xor_sync(0xffffffffu, fb, 16);
}

// ---------------------------------------------------------------------------
// Forward+backward kernel: 1 chain per warp, 2048 warps.
// 2 batches per block (128 threads):
//   warp 0: fwd b0   warp 1: bwd b0   warp 2: fwd b1   warp 3: bwd b1
//
// EMIT STAGING (new): instead of 1 scattered 4B LDG per lane per iter (whose
// exposed DRAM latency at SB-limited MLP ~4-6 was the ~200cyc/iter binder),
// each warp issues ONE coalesced LDG.128 per 4 iterations (lane l -> float4
// of row 4c + l/8, cols (l&7)*4), double-register-buffered 2 chunks ahead
// (8-iter slack), staged through a 4-slot smem ring; per-iter emit is a
// conflict-free LDS.32 hidden under the matvec.
// ---------------------------------------------------------------------------
__global__ __launch_bounds__(128, 4)
void crf_fb_kernel(const float* __restrict__ logits,
                   const float* __restrict__ trans) {
    const int w   = threadIdx.x >> 5;     // warp in block (0..3)
    const int j   = threadIdx.x & 31;     // lane = tag
    const int bi  = w >> 1;               // batch within block (0/1)
    const int dir = w & 1;                // 0 = fwd, 1 = bwd
    const int b   = blockIdx.x * 2 + bi;

    __shared__ __align__(16) float sbuf[4][2][32];       // u exchange
    __shared__ __align__(16) float stage[4][4][4][32];   // [warp][slot][row][tag]
    __shared__ float xg[2][32];                          // gamma_512 exchange
    __shared__ float xacc[2];                            // bwd log-scale

    const int h  = (j >> 4) << 4;         // my half's base index (0 or 16)
    const int jp = j ^ 16;                // partner output tag

    unsigned long long ea[8], eb[8];
    if (dir == 0) {
#pragma unroll
        for (int k = 0; k < 8; k++) {
            ea[k] = pk2(expf(trans[(h + 2 * k) * TAGS + j]),
                        expf(trans[(h + 2 * k + 1) * TAGS + j]));
            eb[k] = pk2(expf(trans[(h + 2 * k) * TAGS + jp]),
                        expf(trans[(h + 2 * k + 1) * TAGS + jp]));
        }
    } else {
#pragma unroll
        for (int k = 0; k < 8; k++) {
            ea[k] = pk2(expf(trans[j * TAGS + h + 2 * k]),
                        expf(trans[j * TAGS + h + 2 * k + 1]));
            eb[k] = pk2(expf(trans[jp * TAGS + h + 2 * k]),
                        expf(trans[jp * TAGS + h + 2 * k + 1]));
        }
    }

    const float* lg = logits + (size_t)b * (SEQ * TAGS);

    // init state (scaled by lane-0 emit)
    float e0 = (dir == 0) ? lg[j] : lg[(SEQ - 1) * TAGS + j];
    float m0 = __shfl_sync(0xffffffffu, e0, 0);
    float u      = ex2f((e0 - m0) * LOG2E);
    float logacc = m0;

    // --- cooperative emit staging setup ---
    // emit row for iter t: fwd 1+t, bwd 1022-t. Chunk c = iters [4c, 4c+4).
    // Lane l covers row q = l>>3 within the chunk, cols (l&7)*4 .. +3.
    const int   q    = j >> 3;            // row-in-chunk this lane loads
    const int   col  = (j & 7) * 4;       // column base this lane loads
    const int   base = (dir == 0) ? 1 : (SEQ - 2);
    const int   step = (dir == 0) ? 1 : -1;
    // gmem float4 address for chunk c: lg + (base + (4c+q)*step)*TAGS + col
    const float* gsrc0 = lg + (size_t)(base + q * step) * TAGS + col;
    const int   gstep  = 4 * step * TAGS;           // advance one chunk
    float* stg = &stage[w][0][0][0];                 // this warp's staging
    const int myoff = q * TAGS + col;                // lane's STS offset in slot

    // fill slots 0,1 with chunks 0,1; prefetch chunks 2,3 into registers
    {
        float4 c0 = *(const float4*)(gsrc0);
        float4 c1 = *(const float4*)(gsrc0 + gstep);
        *(float4*)(stg + 0 * 128 + myoff) = c0;
        *(float4*)(stg + 1 * 128 + myoff) = c1;
    }
    float4 fA = *(const float4*)(gsrc0 + 2 * gstep);  // chunk 2
    float4 fB = *(const float4*)(gsrc0 + 3 * gstep);  // chunk 3
    const float* gnext = gsrc0 + 4 * gstep;           // chunk 4 onward
    __syncwarp(0xffffffffu);

    float* wb0 = &sbuf[w][0][0];
    float* wb1 = &sbuf[w][1][0];

#pragma unroll 4
    for (int it = 0; it < ITERS; ++it) {
        if ((it & 3) == 0) {
            int c = it >> 2;
            // stage chunk c+2 (fetched 8 iters ago), rotate, prefetch c+4
            *(float4*)(stg + ((c + 2) & 3) * 128 + myoff) = fA;
            fA = fB;
            fB = *(const float4*)(gnext);
            gnext += gstep;
        }

        // emit from staging: conflict-free LDS.32, latency hides under matvec
        float emit = stg[((it >> 2) & 3) * 128 + (it & 3) * TAGS + j];

        float u0 = 0.0f;
        if ((it & 3) == 0)
            u0 = __shfl_sync(0xffffffffu, u, 0);   // off-path renorm scale

        float p = ex2f(emit * LOG2E);       // off the carried chain

        float* wb = (it & 1) ? wb1 : wb0;
        wb[j] = u;
        __syncwarp(0xffffffffu);

        float s = matvec_half(wb + h, ea, eb);
        float un = s * p;

        if ((it & 3) == 0) {
            un *= rcpf(u0);
            logacc += lg2f(u0) * LN2;       // off-path bookkeeping
        }
        u = un;
    }

    // final renorm so the meeting dot-product can't overflow
    {
        float u0 = __shfl_sync(0xffffffffu, u, 0);
        u *= rcpf(u0);
        logacc += lg2f(u0) * LN2;
    }

    if (dir == 1) {
        xg[bi][j] = u;                      // gamma_512 (scaled)
        if (j == 0) xacc[bi] = logacc;
    }
    __syncthreads();

    if (dir == 0) {
        // s = E^T alpha_511 (one more matvec, no emit). Parity-1 buffer:
        // its last reads (it=509) are sealed by syncwarp(it=510).
        wb1[j] = u;
        __syncwarp(0xffffffffu);
        float s = matvec_half(wb1 + h, ea, eb);

        float prod = s * xg[bi][j];
#pragma unroll
        for (int k = 16; k; k >>= 1)
            prod += __shfl_xor_sync(0xffffffffu, prod, k);

        if (j == 0)
            g_logz[b] = lg2f(prod) * LN2 + logacc + xacc[bi];
    }
}

// ---------------------------------------------------------------------------
// Gold score: one 256-thread block per batch (gather-latency hiding). Last
// block performs the ticket-fenced deterministic reduction -> mean.
// (Kept as a separate kernel: R9/R14/R16 all showed gold's 32-line gathers
// poison the fb loop under any form of co-residency.)
// ---------------------------------------------------------------------------
__global__ __launch_bounds__(256, 4)
void crf_gold_reduce_kernel(const float* __restrict__ logits,
                            const float* __restrict__ trans,
                            const int* __restrict__ tags,
                            const int* __restrict__ lengths,
                            float* __restrict__ out) {
    __shared__ float tr[TAGS * TAGS];
    __shared__ float sm[8];
    __shared__ bool  amLast;

    for (int i = threadIdx.x; i < TAGS * TAGS; i += blockDim.x)
        tr[i] = trans[i];
    __syncthreads();

    const int b    = blockIdx.x;
    const int tid  = threadIdx.x;
    const int warp = tid >> 5;
    const int l    = tid & 31;

    const int*   tg = tags + (size_t)b * SEQ;
    const float* lg = logits + (size_t)b * (SEQ * TAGS);
    const int len = lengths[b];

    float acc = 0.0f;
    for (int s = tid; s < len; s += 256) {
        int t1 = __ldg(&tg[s]);
        acc += __ldg(&lg[s * TAGS + t1]);
        if (s > 0) {
            int t0 = __ldg(&tg[s - 1]);
            acc += tr[t0 * TAGS + t1];
        }
    }
#pragma unroll
    for (int k = 16; k; k >>= 1)
        acc += __shfl_xor_sync(0xffffffffu, acc, k);
    if (l == 0) sm[warp] = acc;
    __syncthreads();

    if (tid == 0) {
        float gold = 0.0f;
#pragma unroll
        for (int qq = 0; qq < 8; qq++) gold += sm[qq];
        g_partial[b] = g_logz[b] - gold;
        __threadfence();
        unsigned int t = atomicAdd(&g_ticket, 1u);
        amLast = (t == (unsigned)(BATCH - 1));
    }
    __syncthreads();

    if (amLast) {
        __shared__ float red[256];
        float a = 0.0f;
#pragma unroll
        for (int o = 0; o < 4; o++)
            a += __ldcg(&g_partial[tid + o * 256]);
        red[tid] = a;
        __syncthreads();
#pragma unroll
        for (int k = 128; k; k >>= 1) {
            if (tid < k) red[tid] += red[tid + k];
            __syncthreads();
        }
        if (tid == 0) {
            out[0] = red[0] * (1.0f / 1024.0f);
            g_ticket = 0;                  // reset for next graph replay
        }
    }
}

extern "C" void kernel_launch(void* const* d_in, const int* in_sizes, int n_in,
                              void* d_out, int out_size) {
    const float* logits  = (const float*)d_in[0];
    const float* trans   = (const float*)d_in[1];
    const int*   tags    = (const int*)d_in[2];
    const int*   lengths = (const int*)d_in[3];
    float* out = (float*)d_out;

    crf_fb_kernel<<<BATCH / 2, 128>>>(logits, trans);
    crf_gold_reduce_kernel<<<BATCH, 256>>>(logits, trans, tags, lengths, out);
}